// round 6
// baseline (speedup 1.0000x reference)
#include <cuda_runtime.h>
#include <cuda_fp16.h>
#include <math.h>
#include <stdint.h>

// Problem constants
#define BB 32
#define NN 4096
#define DD 512
#define CC 64
#define RTOT (BB*NN)          // 131072 rows
#define MT 32                 // rows per GEMM tile
#define NTILES (RTOT/MT)      // 4096
#define DP 65                 // dots pitch (conflict-free stores/loads)
#define CHUNK 128             // rows per feature chunk
#define NCHUNK (NN/CHUNK)     // 32

// smem byte offsets (per CTA total 115456 B -> 2 CTAs/SM)
#define SM_ANCH  0                    // 64x512 fp16 swizzled = 65536
#define SM_X     65536                // 32x512 fp16 swizzled = 32768
#define SM_DOTS  98304                // 2 x 32 x DP f32 = 16640
#define SM_ANORM 114944               // 64 f32
#define SM_NORM  115200               // 32 f32
#define SM_MASK  115328               // 32 i32
#define SM_TOTAL 115456

// Device scratch (allocation-free rule: __device__ globals)
__device__ float g_sw[(size_t)RTOT*CC];          // score*invnorm*valid, 32 MiB
__device__ int   g_counts[BB*CC];
__device__ int   g_index[BB];
__device__ float g_part[(size_t)BB*NCHUNK*DD];   // 2 MiB

// mask may be int64 (jax x64) or int32. Values in [1,4096]: if int64 LE,
// word 1 (high half of elem 0) is 0.
__device__ __forceinline__ int decode_mask(const int* mr, int b) {
    return (mr[1] == 0) ? mr[2*b] : mr[b];
}

__device__ __forceinline__ unsigned h2u(float a, float b) {
    __half2 h = __floats2half2_rn(a, b);
    return *(unsigned*)&h;
}

__device__ __forceinline__ uint32_t smem_u32(const void* p) {
    uint32_t a;
    asm("{ .reg .u64 t; cvta.to.shared.u64 t, %1; cvt.u32.u64 %0, t; }" : "=r"(a) : "l"(p));
    return a;
}

__device__ __forceinline__ void ldsm_x4(unsigned& r0, unsigned& r1, unsigned& r2,
                                        unsigned& r3, uint32_t addr) {
    asm volatile("ldmatrix.sync.aligned.m8n8.x4.shared.b16 {%0,%1,%2,%3}, [%4];"
                 : "=r"(r0), "=r"(r1), "=r"(r2), "=r"(r3) : "r"(addr));
}

__device__ __forceinline__ void mma_f16(float* d,
                                        unsigned a0, unsigned a1, unsigned a2, unsigned a3,
                                        unsigned b0, unsigned b1) {
    asm volatile("mma.sync.aligned.m16n8k16.row.col.f32.f16.f16.f32 "
                 "{%0,%1,%2,%3}, {%4,%5,%6,%7}, {%8,%9}, {%0,%1,%2,%3};"
                 : "+f"(d[0]), "+f"(d[1]), "+f"(d[2]), "+f"(d[3])
                 : "r"(a0), "r"(a1), "r"(a2), "r"(a3), "r"(b0), "r"(b1));
}

__global__ __launch_bounds__(256, 2)
void main_kernel(const float* __restrict__ x, const int* __restrict__ maskr,
                 const float* __restrict__ anchors) {
    extern __shared__ __align__(1024) char smem[];
    const uint32_t sb = smem_u32(smem);
    float* dots_s  = (float*)(smem + SM_DOTS);
    float* anorm_s = (float*)(smem + SM_ANORM);
    float* norm_s  = (float*)(smem + SM_NORM);
    int*   mask_s  = (int*)(smem + SM_MASK);

    const int tid = threadIdx.x, lane = tid & 31, warp = tid >> 5;  // 8 warps

    // ---- anchors -> fp16 smem, 16B-chunk XOR swizzle: chunk' = chunk ^ (c&7) ----
    for (int i = tid; i < CC*DD; i += 256) {
        int c = i >> 9, k = i & (DD-1);
        uint32_t off = (uint32_t)(c*1024 + (((k>>3) ^ (c&7))<<4) + (k&7)*2);
        *(__half*)(smem + SM_ANCH + off) = __float2half_rn(anchors[i]);
    }
    if (tid < BB) mask_s[tid] = decode_mask(maskr, tid);
    if (tid < CC) {
        float s = 0.f;
        const float* ar = anchors + (size_t)tid*DD;
        #pragma unroll 8
        for (int k = 0; k < DD; k++) { float q = ar[k]; s = fmaf(q, q, s); }
        anorm_s[tid] = s;
    }
    __syncthreads();

    // warp decomposition: ms(2) x ns(2) x kh(2)
    const int ms = warp & 1, ns = (warp >> 1) & 1, kh = warp >> 2;
    const int gid = lane >> 2, tig = lane & 3;

    // ldmatrix address precompute
    const int arow = ms*16 + (lane & 15);
    const uint32_t pA  = sb + SM_X + arow*1024;
    const int xrA = arow & 7;
    const int cA0 = kh*32 + (lane >> 4);
    const int bcol = ns*32 + ((lane >> 4) << 3) + (lane & 7);
    const uint32_t pB0 = sb + SM_ANCH + bcol*1024;
    const uint32_t pB1 = pB0 + 16*1024;
    const int xrB = lane & 7;
    const int cB0 = kh*32 + ((lane >> 3) & 1);

    // x load/store mapping: row r = tid>>3, chunk slot = tid&7 (+8j)
    const int r = tid >> 3, cs = tid & 7;

    // ---- find first valid tile, prefetch raw fp32 ----
    int tile = blockIdx.x;
    while (tile < NTILES) {
        int bb = (tile*MT) >> 12;
        if (((tile*MT) & (NN-1)) < mask_s[bb]) break;
        tile += gridDim.x;
    }
    float4 v[16];
    if (tile < NTILES) {
        const float4* xg = (const float4*)x + (size_t)tile*4096 + r*128 + cs*2;
        #pragma unroll
        for (int j = 0; j < 8; j++) { v[2*j] = xg[16*j]; v[2*j+1] = xg[16*j+1]; }
    }

    while (tile < NTILES) {
        const int rowbase = tile*MT;
        const int b = rowbase >> 12;

        // ---- convert+store x tile (swizzled fp16) + row norm ----
        float ns_acc = 0.f;
        #pragma unroll
        for (int j = 0; j < 8; j++) {
            float4 q0 = v[2*j], q1 = v[2*j+1];
            uint4 st;
            st.x = h2u(q0.x, q0.y); st.y = h2u(q0.z, q0.w);
            st.z = h2u(q1.x, q1.y); st.w = h2u(q1.z, q1.w);
            int chunk = cs + 8*j;
            *(uint4*)(smem + SM_X + r*1024 + ((chunk ^ (r&7))<<4)) = st;
            ns_acc = fmaf(q0.x,q0.x, fmaf(q0.y,q0.y, fmaf(q0.z,q0.z, fmaf(q0.w,q0.w, ns_acc))));
            ns_acc = fmaf(q1.x,q1.x, fmaf(q1.y,q1.y, fmaf(q1.z,q1.z, fmaf(q1.w,q1.w, ns_acc))));
        }
        ns_acc += __shfl_xor_sync(0xffffffffu, ns_acc, 1);
        ns_acc += __shfl_xor_sync(0xffffffffu, ns_acc, 2);
        ns_acc += __shfl_xor_sync(0xffffffffu, ns_acc, 4);
        if ((lane & 7) == 0) norm_s[r] = ns_acc;
        __syncthreads();

        // ---- find + prefetch next valid tile (overlaps mma + epilogue) ----
        int nt = tile + gridDim.x;
        while (nt < NTILES) {
            int nb = (nt*MT) >> 12;
            if (((nt*MT) & (NN-1)) < mask_s[nb]) break;
            nt += gridDim.x;
        }
        if (nt < NTILES) {
            const float4* xg = (const float4*)x + (size_t)nt*4096 + r*128 + cs*2;
            #pragma unroll
            for (int j = 0; j < 8; j++) { v[2*j] = xg[16*j]; v[2*j+1] = xg[16*j+1]; }
        }

        // ---- mma: warp = 16 rows x 32 cols x 256 k-halves (16 steps) ----
        float acc[4][4];
        #pragma unroll
        for (int g = 0; g < 4; g++)
            { acc[g][0]=0.f; acc[g][1]=0.f; acc[g][2]=0.f; acc[g][3]=0.f; }
        #pragma unroll
        for (int ks = 0; ks < 16; ks++) {
            unsigned a0,a1,a2,a3, b0,b1,b2,b3, b4,b5,b6,b7;
            ldsm_x4(a0,a1,a2,a3, pA  + (((2*ks + cA0) ^ xrA) << 4));
            ldsm_x4(b0,b1,b2,b3, pB0 + (((2*ks + cB0) ^ xrB) << 4));
            ldsm_x4(b4,b5,b6,b7, pB1 + (((2*ks + cB0) ^ xrB) << 4));
            mma_f16(acc[0], a0,a1,a2,a3, b0,b1);
            mma_f16(acc[1], a0,a1,a2,a3, b2,b3);
            mma_f16(acc[2], a0,a1,a2,a3, b4,b5);
            mma_f16(acc[3], a0,a1,a2,a3, b6,b7);
        }
        {
            float* dh = dots_s + kh*(32*DP);
            const int r0 = ms*16 + gid, r1 = r0 + 8;
            #pragma unroll
            for (int g = 0; g < 4; g++) {
                int col = ns*32 + g*8 + 2*tig;
                dh[r0*DP + col]     = acc[g][0];
                dh[r0*DP + col + 1] = acc[g][1];
                dh[r1*DP + col]     = acc[g][2];
                dh[r1*DP + col + 1] = acc[g][3];
            }
        }
        __syncthreads();

        // ---- epilogue: 4 rows per warp ----
        #pragma unroll
        for (int u = 0; u < 4; u++) {
            const int m = warp*4 + u;
            const int row = rowbase + m;
            const int n = row & (NN-1);
            const bool valid = n < mask_s[b];
            const float n2  = norm_s[m];
            const float inv = 1.f / fmaxf(sqrtf(n2), 1e-12f);
            const float sxn2 = n2 * inv * inv;
            const int cA = lane, cB = lane + 32;
            const float dA = dots_s[m*DP + cA] + dots_s[32*DP + m*DP + cA];
            const float dB = dots_s[m*DP + cB] + dots_s[32*DP + m*DP + cB];
            const float sqA = sxn2 + anorm_s[cA] - 2.f*dA*inv;
            const float sqB = sxn2 + anorm_s[cB] - 2.f*dB*inv;
            const float idA = rsqrtf(fmaxf(sqA, 1e-30f));
            const float idB = rsqrtf(fmaxf(sqB, 1e-30f));
            float mx = fmaxf(idA, idB);
            #pragma unroll
            for (int o = 16; o; o >>= 1) mx = fmaxf(mx, __shfl_xor_sync(0xffffffffu, mx, o));
            const float eA = __expf(idA - mx), eB = __expf(idB - mx);
            float ss = eA + eB;
            #pragma unroll
            for (int o = 16; o; o >>= 1) ss += __shfl_xor_sync(0xffffffffu, ss, o);
            const float rs = 1.f / ss;
            const size_t base = (size_t)row * CC;
            g_sw[base + cA] = valid ? eA*rs*inv : 0.f;
            g_sw[base + cB] = valid ? eB*rs*inv : 0.f;
            float bv; int bi;
            if (idB > idA) { bv = idB; bi = cB; } else { bv = idA; bi = cA; }
            #pragma unroll
            for (int o = 16; o; o >>= 1) {
                float ov = __shfl_xor_sync(0xffffffffu, bv, o);
                int   oi = __shfl_xor_sync(0xffffffffu, bi, o);
                if (ov > bv || (ov == bv && oi < bi)) { bv = ov; bi = oi; }
            }
            if (lane == 0 && valid) atomicAdd(&g_counts[b*CC + bi], 1);
        }
        __syncthreads();
        tile = nt;
    }
}

// argmax of counts per batch; also resets counts for the next graph replay
__global__ void index_kernel() {
    __shared__ int sv[CC], si[CC];
    const int b = blockIdx.x, c = threadIdx.x;
    sv[c] = g_counts[b*CC + c]; si[c] = c;
    g_counts[b*CC + c] = 0;
    __syncthreads();
    for (int o = 32; o; o >>= 1) {
        if (c < o) {
            if (sv[c+o] > sv[c] || (sv[c+o] == sv[c] && si[c+o] < si[c])) {
                sv[c] = sv[c+o]; si[c] = si[c+o];
            }
        }
        __syncthreads();
    }
    if (c == 0) g_index[b] = si[0];
}

__global__ __launch_bounds__(256)
void feat_part_kernel(const float* __restrict__ x, const int* __restrict__ maskr) {
    const int b = blockIdx.y, ch = blockIdx.x;
    const int tid = threadIdx.x;
    __shared__ float w_s[CHUNK];
    __shared__ int s_idx, s_nv;
    if (tid == 0) {
        s_idx = g_index[b];
        int nv = decode_mask(maskr, b) - ch*CHUNK;
        s_nv = nv < 0 ? 0 : (nv > CHUNK ? CHUNK : nv);
    }
    __syncthreads();
    const int nv = s_nv;
    float* gp = g_part + ((size_t)b*NCHUNK + ch)*DD;
    if (nv == 0) {
        ((float2*)gp)[tid] = make_float2(0.f, 0.f);
        return;
    }
    const int idx = s_idx;
    const int rowbase = b*NN + ch*CHUNK;
    if (tid < CHUNK) w_s[tid] = (tid < nv) ? g_sw[(size_t)(rowbase + tid)*CC + idx] : 0.f;
    __syncthreads();
    float ax = 0.f, ay = 0.f;
    const float2* xb = (const float2*)(x + (size_t)rowbase*DD);
    int r = 0;
    for (; r + 16 <= nv; r += 16) {
        float2 vv[16];
        #pragma unroll
        for (int u = 0; u < 16; u++) vv[u] = xb[(size_t)(r+u)*256 + tid];
        #pragma unroll
        for (int u = 0; u < 16; u++) {
            float w = w_s[r+u];
            ax = fmaf(vv[u].x, w, ax);
            ay = fmaf(vv[u].y, w, ay);
        }
    }
    for (; r < nv; r++) {
        float2 vv = xb[(size_t)r*256 + tid];
        float w = w_s[r];
        ax = fmaf(vv.x, w, ax);
        ay = fmaf(vv.y, w, ay);
    }
    ((float2*)gp)[tid] = make_float2(ax, ay);
}

__global__ void feat_reduce_kernel(float* __restrict__ out) {
    const int i = blockIdx.x*blockDim.x + threadIdx.x;  // BB*DD = 16384
    const int b = i >> 9, d = i & (DD-1);
    float s = 0.f;
    #pragma unroll 8
    for (int ch = 0; ch < NCHUNK; ch++) s += g_part[((size_t)b*NCHUNK + ch)*DD + d];
    out[i] = s;
}

extern "C" void kernel_launch(void* const* d_in, const int* in_sizes, int n_in,
                              void* d_out, int out_size) {
    const float* x       = (const float*)d_in[0];
    const int*   mask    = (const int*)d_in[1];
    const float* anchors = (const float*)d_in[2];
    float* out = (float*)d_out;

    cudaFuncSetAttribute(main_kernel, cudaFuncAttributeMaxDynamicSharedMemorySize, SM_TOTAL);

    main_kernel<<<304, 256, SM_TOTAL>>>(x, mask, anchors);
    index_kernel<<<BB, CC>>>();
    dim3 g(NCHUNK, BB);
    feat_part_kernel<<<g, 256>>>(x, mask);
    feat_reduce_kernel<<<BB*DD/256, 256>>>(out);
}

// round 7
// speedup vs baseline: 1.2029x; 1.2029x over previous
#include <cuda_runtime.h>
#include <cuda_fp16.h>
#include <math.h>
#include <stdint.h>

// Problem constants
#define BB 32
#define NN 4096
#define DD 512
#define CC 64
#define RTOT (BB*NN)          // 131072 rows
#define MT 32                 // rows per GEMM tile
#define NTILES (RTOT/MT)      // 4096
#define XPH 520               // x_s pitch in halves: 260 words ≡ 4 (mod 32) -> conflict-free
#define APH 520               // anchor pitch in halves
#define DP 65                 // dots pitch in floats (conflict-free stores)
#define CHUNK 128             // rows per feature chunk
#define NCHUNK (NN/CHUNK)     // 32

// Device scratch (allocation-free rule: __device__ globals)
__device__ float g_sw[(size_t)RTOT*CC];          // score*invnorm*valid, 32 MiB
__device__ int   g_counts[BB*CC];
__device__ int   g_index[BB];
__device__ float g_part[(size_t)BB*NCHUNK*DD];   // 2 MiB

// mask may be int64 (jax x64) or int32. Values in [1,4096]: if int64 LE,
// word 1 (high half of elem 0) is 0.
__device__ __forceinline__ int decode_mask(const int* mr, int b) {
    return (mr[1] == 0) ? mr[2*b] : mr[b];
}

__device__ __forceinline__ void mma_f16(float& d0, float& d1, float& d2, float& d3,
                                        unsigned a0, unsigned a1, unsigned a2, unsigned a3,
                                        unsigned b0, unsigned b1) {
    asm volatile("mma.sync.aligned.m16n8k16.row.col.f32.f16.f16.f32 "
                 "{%0,%1,%2,%3}, {%4,%5,%6,%7}, {%8,%9}, {%0,%1,%2,%3};"
                 : "+f"(d0), "+f"(d1), "+f"(d2), "+f"(d3)
                 : "r"(a0), "r"(a1), "r"(a2), "r"(a3), "r"(b0), "r"(b1));
}

__global__ __launch_bounds__(512, 1)
void main_kernel(const float* __restrict__ x, const int* __restrict__ maskr,
                 const float* __restrict__ anchors) {
    extern __shared__ char smem[];
    __half*   a_h    = (__half*)smem;                    // [CC][APH] anchors fp16
    __half*   x_h    = a_h + CC*APH;                     // [2][MT][XPH] x tile fp16
    float*    dots_s = (float*)(x_h + 2*MT*XPH);         // [2][2][MT][DP]
    float*    anorm_s= dots_s + 4*MT*DP;                 // [CC]
    float*    norm_s = anorm_s + CC;                     // [2][MT]
    int*      mask_s = (int*)(norm_s + 2*MT);            // [BB]

    const int tid  = threadIdx.x;
    const int lane = tid & 31, warp = tid >> 5;           // 16 warps

    // ---- anchors -> smem fp16, [c][k] pitch APH ----
    for (int i = tid; i < CC*DD; i += 512) {
        int c = i >> 9, k = i & (DD-1);
        a_h[c*APH + k] = __float2half_rn(anchors[i]);
    }
    if (tid < BB) mask_s[tid] = decode_mask(maskr, tid);
    if (tid < CC) {
        float s = 0.f;
        const float* ar = anchors + (size_t)tid*DD;
        #pragma unroll 8
        for (int k = 0; k < DD; k++) { float q = ar[k]; s = fmaf(q, q, s); }
        anorm_s[tid] = s;
    }
    __syncthreads();

    // warp decomposition: mslice (2) x nslice (4) x khalf (2)
    const int gid = lane >> 2, tig = lane & 3;
    const int mbase = (warp & 1) * 16;
    const int nb0   = ((warp >> 1) & 3) * 16;
    const int kh    = warp >> 3;

    // load mapping: thread -> one row, 8 float4 slots
    const int lrow  = tid >> 4;                  // 0..31
    const int lslot = tid & 15;

    // ---- find first valid tile, prefetch ----
    int tile = blockIdx.x;
    while (tile < NTILES) {
        int bb = (tile*MT) >> 12;
        if (((tile*MT) & (NN-1)) < mask_s[bb]) break;
        tile += gridDim.x;
    }
    float4 v[8];
    if (tile < NTILES) {
        const float4* xg = (const float4*)(x + (size_t)tile*MT*DD) + lrow*128 + lslot;
        #pragma unroll
        for (int j = 0; j < 8; j++) v[j] = xg[16*j];
    }

    int prev = -1, prevbase = 0, prevb = 0;
    int p = 0;

    while (tile < NTILES) {
        const int rowbase = tile*MT;
        const int b = rowbase >> 12;

        // ---- store tile to x_h[p] (fp16) + row norm from fp32 registers ----
        float nacc = 0.f;
        {
            char* xrow = (char*)(x_h + p*MT*XPH) + lrow*(XPH*2);
            #pragma unroll
            for (int j = 0; j < 8; j++) {
                float4 q = v[j];
                __half2 h01 = __floats2half2_rn(q.x, q.y);
                __half2 h23 = __floats2half2_rn(q.z, q.w);
                uint2 st;
                st.x = *(unsigned*)&h01;
                st.y = *(unsigned*)&h23;
                *(uint2*)(xrow + (lslot + 16*j)*8) = st;
                nacc = fmaf(q.x,q.x, fmaf(q.y,q.y, fmaf(q.z,q.z, fmaf(q.w,q.w, nacc))));
            }
        }
        #pragma unroll
        for (int o = 8; o; o >>= 1) nacc += __shfl_xor_sync(0xffffffffu, nacc, o);
        if ((lane & 15) == 0) norm_s[p*MT + lrow] = nacc;
        __syncthreads();   // the ONLY barrier per tile

        // ---- find + prefetch next valid tile (overlaps mma + epilogue) ----
        int nt = tile + gridDim.x;
        while (nt < NTILES) {
            int nb = (nt*MT) >> 12;
            if (((nt*MT) & (NN-1)) < mask_s[nb]) break;
            nt += gridDim.x;
        }
        if (nt < NTILES) {
            const float4* xg = (const float4*)(x + (size_t)nt*MT*DD) + lrow*128 + lslot;
            #pragma unroll
            for (int j = 0; j < 8; j++) v[j] = xg[16*j];
        }

        // ---- fp16 mma: warp = 16 rows x 16 cols over its k-half -> dots[p] ----
        {
            float d00=0,d01=0,d02=0,d03=0, d10=0,d11=0,d12=0,d13=0;
            const __half* xa  = x_h + p*MT*XPH + (mbase + gid)*XPH + kh*256 + 2*tig;
            const __half* b0p = a_h + (nb0 + gid)*APH     + kh*256 + 2*tig;
            const __half* b1p = a_h + (nb0 + gid + 8)*APH + kh*256 + 2*tig;
            #pragma unroll
            for (int k0 = 0; k0 < 256; k0 += 16) {
                unsigned a0 = *(const unsigned*)(xa + k0);
                unsigned a1 = *(const unsigned*)(xa + 8*XPH + k0);
                unsigned a2 = *(const unsigned*)(xa + k0 + 8);
                unsigned a3 = *(const unsigned*)(xa + 8*XPH + k0 + 8);
                unsigned b00 = *(const unsigned*)(b0p + k0);
                unsigned b01 = *(const unsigned*)(b0p + k0 + 8);
                unsigned b10 = *(const unsigned*)(b1p + k0);
                unsigned b11 = *(const unsigned*)(b1p + k0 + 8);
                mma_f16(d00,d01,d02,d03, a0,a1,a2,a3, b00,b01);
                mma_f16(d10,d11,d12,d13, a0,a1,a2,a3, b10,b11);
            }
            float* dh = dots_s + (p*2 + kh)*MT*DP;
            const int r0 = mbase + gid, r1 = r0 + 8, cb = 2*tig;
            dh[r0*DP + nb0 + cb]     = d00;
            dh[r0*DP + nb0 + cb + 1] = d01;
            dh[r1*DP + nb0 + cb]     = d02;
            dh[r1*DP + nb0 + cb + 1] = d03;
            dh[r0*DP + nb0 + 8 + cb]     = d10;
            dh[r0*DP + nb0 + 8 + cb + 1] = d11;
            dh[r1*DP + nb0 + 8 + cb]     = d12;
            dh[r1*DP + nb0 + 8 + cb + 1] = d13;
        }

        // ---- deferred epilogue for prev tile (reads buffers p^1) ----
        if (prev >= 0) {
            const int q = p ^ 1;
            const float* ds = dots_s + q*2*MT*DP;
            #pragma unroll
            for (int u = 0; u < 2; u++) {
                const int m = warp*2 + u;
                const int row = prevbase + m;
                const int n = row & (NN-1);
                const bool valid = n < mask_s[prevb];
                const float n2  = norm_s[q*MT + m];
                const float inv = 1.f / fmaxf(sqrtf(n2), 1e-12f);
                const float sxn2 = n2 * inv * inv;
                const int cA = lane, cB = lane + 32;
                const float dA = ds[m*DP + cA] + ds[MT*DP + m*DP + cA];
                const float dB = ds[m*DP + cB] + ds[MT*DP + m*DP + cB];
                const float sqA = sxn2 + anorm_s[cA] - 2.f*dA*inv;
                const float sqB = sxn2 + anorm_s[cB] - 2.f*dB*inv;
                const float idA = rsqrtf(fmaxf(sqA, 1e-30f));
                const float idB = rsqrtf(fmaxf(sqB, 1e-30f));
                float mx = fmaxf(idA, idB);
                #pragma unroll
                for (int o = 16; o; o >>= 1) mx = fmaxf(mx, __shfl_xor_sync(0xffffffffu, mx, o));
                const float eA = __expf(idA - mx), eB = __expf(idB - mx);
                float ss = eA + eB;
                #pragma unroll
                for (int o = 16; o; o >>= 1) ss += __shfl_xor_sync(0xffffffffu, ss, o);
                const float rs = 1.f / ss;
                const size_t base = (size_t)row * CC;
                g_sw[base + cA] = valid ? eA*rs*inv : 0.f;
                g_sw[base + cB] = valid ? eB*rs*inv : 0.f;
                float bv; int bi;
                if (idB > idA) { bv = idB; bi = cB; } else { bv = idA; bi = cA; }
                #pragma unroll
                for (int o = 16; o; o >>= 1) {
                    float ov = __shfl_xor_sync(0xffffffffu, bv, o);
                    int   oi = __shfl_xor_sync(0xffffffffu, bi, o);
                    if (ov > bv || (ov == bv && oi < bi)) { bv = ov; bi = oi; }
                }
                if (lane == 0 && valid) atomicAdd(&g_counts[prevb*CC + bi], 1);
            }
        }

        prev = tile; prevbase = rowbase; prevb = b;
        tile = nt; p ^= 1;
    }

    // ---- final epilogue (last tile's dots live in buffer p^1) ----
    if (prev >= 0) {
        __syncthreads();
        const int q = p ^ 1;
        const float* ds = dots_s + q*2*MT*DP;
        #pragma unroll
        for (int u = 0; u < 2; u++) {
            const int m = warp*2 + u;
            const int row = prevbase + m;
            const int n = row & (NN-1);
            const bool valid = n < mask_s[prevb];
            const float n2  = norm_s[q*MT + m];
            const float inv = 1.f / fmaxf(sqrtf(n2), 1e-12f);
            const float sxn2 = n2 * inv * inv;
            const int cA = lane, cB = lane + 32;
            const float dA = ds[m*DP + cA] + ds[MT*DP + m*DP + cA];
            const float dB = ds[m*DP + cB] + ds[MT*DP + m*DP + cB];
            const float sqA = sxn2 + anorm_s[cA] - 2.f*dA*inv;
            const float sqB = sxn2 + anorm_s[cB] - 2.f*dB*inv;
            const float idA = rsqrtf(fmaxf(sqA, 1e-30f));
            const float idB = rsqrtf(fmaxf(sqB, 1e-30f));
            float mx = fmaxf(idA, idB);
            #pragma unroll
            for (int o = 16; o; o >>= 1) mx = fmaxf(mx, __shfl_xor_sync(0xffffffffu, mx, o));
            const float eA = __expf(idA - mx), eB = __expf(idB - mx);
            float ss = eA + eB;
            #pragma unroll
            for (int o = 16; o; o >>= 1) ss += __shfl_xor_sync(0xffffffffu, ss, o);
            const float rs = 1.f / ss;
            const size_t base = (size_t)row * CC;
            g_sw[base + cA] = valid ? eA*rs*inv : 0.f;
            g_sw[base + cB] = valid ? eB*rs*inv : 0.f;
            float bv; int bi;
            if (idB > idA) { bv = idB; bi = cB; } else { bv = idA; bi = cA; }
            #pragma unroll
            for (int o = 16; o; o >>= 1) {
                float ov = __shfl_xor_sync(0xffffffffu, bv, o);
                int   oi = __shfl_xor_sync(0xffffffffu, bi, o);
                if (ov > bv || (ov == bv && oi < bi)) { bv = ov; bi = oi; }
            }
            if (lane == 0 && valid) atomicAdd(&g_counts[prevb*CC + bi], 1);
        }
    }
}

// argmax of counts per batch; also resets counts for the next graph replay
__global__ void index_kernel() {
    __shared__ int sv[CC], si[CC];
    const int b = blockIdx.x, c = threadIdx.x;
    sv[c] = g_counts[b*CC + c]; si[c] = c;
    g_counts[b*CC + c] = 0;
    __syncthreads();
    for (int o = 32; o; o >>= 1) {
        if (c < o) {
            if (sv[c+o] > sv[c] || (sv[c+o] == sv[c] && si[c+o] < si[c])) {
                sv[c] = sv[c+o]; si[c] = si[c+o];
            }
        }
        __syncthreads();
    }
    if (c == 0) g_index[b] = si[0];
}

__global__ __launch_bounds__(256)
void feat_part_kernel(const float* __restrict__ x, const int* __restrict__ maskr) {
    const int b = blockIdx.y, ch = blockIdx.x;
    const int tid = threadIdx.x;
    __shared__ float w_s[CHUNK];
    __shared__ int s_idx, s_nv;
    if (tid == 0) {
        s_idx = g_index[b];
        int nv = decode_mask(maskr, b) - ch*CHUNK;
        s_nv = nv < 0 ? 0 : (nv > CHUNK ? CHUNK : nv);
    }
    __syncthreads();
    const int nv = s_nv;
    float* gp = g_part + ((size_t)b*NCHUNK + ch)*DD;
    if (nv == 0) {
        ((float2*)gp)[tid] = make_float2(0.f, 0.f);
        return;
    }
    const int idx = s_idx;
    const int rowbase = b*NN + ch*CHUNK;
    if (tid < CHUNK) w_s[tid] = (tid < nv) ? g_sw[(size_t)(rowbase + tid)*CC + idx] : 0.f;
    __syncthreads();
    float ax = 0.f, ay = 0.f;
    const float2* xb = (const float2*)(x + (size_t)rowbase*DD);
    int r = 0;
    for (; r + 8 <= nv; r += 8) {
        float2 vv[8];
        #pragma unroll
        for (int u = 0; u < 8; u++) vv[u] = xb[(size_t)(r+u)*256 + tid];
        #pragma unroll
        for (int u = 0; u < 8; u++) {
            float w = w_s[r+u];
            ax = fmaf(vv[u].x, w, ax);
            ay = fmaf(vv[u].y, w, ay);
        }
    }
    for (; r < nv; r++) {
        float2 vv = xb[(size_t)r*256 + tid];
        float w = w_s[r];
        ax = fmaf(vv.x, w, ax);
        ay = fmaf(vv.y, w, ay);
    }
    ((float2*)gp)[tid] = make_float2(ax, ay);
}

__global__ void feat_reduce_kernel(float* __restrict__ out) {
    const int i = blockIdx.x*blockDim.x + threadIdx.x;  // BB*DD = 16384
    const int b = i >> 9, d = i & (DD-1);
    float s = 0.f;
    #pragma unroll 8
    for (int ch = 0; ch < NCHUNK; ch++) s += g_part[((size_t)b*NCHUNK + ch)*DD + d];
    out[i] = s;
}

extern "C" void kernel_launch(void* const* d_in, const int* in_sizes, int n_in,
                              void* d_out, int out_size) {
    const float* x       = (const float*)d_in[0];
    const int*   mask    = (const int*)d_in[1];
    const float* anchors = (const float*)d_in[2];
    float* out = (float*)d_out;

    const size_t smem = (size_t)(CC*APH + 2*MT*XPH)*sizeof(__half)
                      + (size_t)(4*MT*DP + CC + 2*MT)*sizeof(float)
                      + BB*sizeof(int);   // ~163 KB
    cudaFuncSetAttribute(main_kernel, cudaFuncAttributeMaxDynamicSharedMemorySize, (int)smem);

    main_kernel<<<152, 512, smem>>>(x, mask, anchors);
    index_kernel<<<BB, CC>>>();
    dim3 g(NCHUNK, BB);
    feat_part_kernel<<<g, 256>>>(x, mask);
    feat_reduce_kernel<<<BB*DD/256, 256>>>(out);
}